// round 2
// baseline (speedup 1.0000x reference)
#include <cuda_runtime.h>

// DMTSkeletonize: exact squared-EDT (brute force, bit-exact vs reference) +
// separable 3x3x3 local-max skeleton computed on d^2 (sqrt is monotone and
// injective on the attainable value set, so comparisons are identical).
//
// Shapes: img [4,1,160,160,160] fp32. B=4, D=H=W=160.

#define WW    160
#define HWSZ  25600      // H*W
#define DHWSZ 4096000    // D*H*W
#define NTOT  16384000   // B*D*H*W
#define FINF  1e12f

// Scratch (device globals — no allocation anywhere, per harness rules)
__device__ float g_A[NTOT];
__device__ float g_B[NTOT];
__device__ float g_C[NTOT];

// ---------------------------------------------------------------------------
// EDT 1D pass: out[line][i] = min_j fl(f[line][j] + (i-j)^2)
// MODE 0: lines along x (contiguous); input = img, binarized; writes g_A
// MODE 1: lines along y (stride W);   g_A -> g_B
// MODE 2: lines along z (stride H*W); g_B -> g_A
// Block: 256 threads, 32 lines/block. 8 warps x 4 lines, 5 outputs/lane.
// ---------------------------------------------------------------------------
template <int MODE>
__global__ __launch_bounds__(256) void edt_pass_kernel(const float* __restrict__ img)
{
    __shared__ float fsh[32][161];  // pad to 161: conflict-free transposed access

    const float* __restrict__ in  = (MODE == 0) ? img : (MODE == 1 ? g_A : g_B);
    float* __restrict__       out = (MODE == 1) ? g_B : g_A;

    const int tid = threadIdx.x;
    const int bid = blockIdx.x;

    long base;
    int stride;
    if (MODE == 0) {
        base = (long)bid * (32 * 160);
        stride = 1;
    } else if (MODE == 1) {
        int p  = bid / 5;            // p = b*160 + z
        int x0 = (bid % 5) * 32;
        base = (long)p * HWSZ + x0;
        stride = WW;
    } else {
        int p  = bid / 5;            // p = b*160 + y
        int x0 = (bid % 5) * 32;
        int b = p / 160, y = p - b * 160;
        base = (long)b * DHWSZ + (long)y * WW + x0;
        stride = HWSZ;
    }

    // ---- load tile into shared ----
    if (MODE == 0) {
        for (int idx = tid; idx < 32 * 160; idx += 256) {
            int l = idx / 160;
            int j = idx - l * 160;
            float v = in[base + idx];                 // contiguous
            fsh[l][j] = (v > 0.5f) ? 0.0f : FINF;     // binarize + invert
        }
    } else {
        for (int idx = tid; idx < 32 * 160; idx += 256) {
            int j = idx >> 5;
            int l = idx & 31;
            fsh[l][j] = in[base + (long)j * stride + l];   // 128B coalesced
        }
    }
    __syncthreads();

    // ---- brute-force min-plus parabola transform ----
    const int warp = tid >> 5;
    const int lane = tid & 31;
    const int l0 = warp * 4;

    float acc[4][5];
#pragma unroll
    for (int a = 0; a < 4; a++)
#pragma unroll
        for (int k = 0; k < 5; k++) acc[a][k] = 3.0e38f;

    float dk[5];
#pragma unroll
    for (int k = 0; k < 5; k++) dk[k] = (float)(lane + 32 * k);  // i - j at j=0

#pragma unroll 2
    for (int j = 0; j < 160; j++) {
        float f0 = fsh[l0 + 0][j];
        float f1 = fsh[l0 + 1][j];
        float f2 = fsh[l0 + 2][j];
        float f3 = fsh[l0 + 3][j];
#pragma unroll
        for (int k = 0; k < 5; k++) {
            float t = dk[k];
            acc[0][k] = fminf(acc[0][k], fmaf(t, t, f0));
            acc[1][k] = fminf(acc[1][k], fmaf(t, t, f1));
            acc[2][k] = fminf(acc[2][k], fmaf(t, t, f2));
            acc[3][k] = fminf(acc[3][k], fmaf(t, t, f3));
            dk[k] = t - 1.0f;
        }
    }

    // ---- stage results through shared for coalesced stores ----
    __syncthreads();   // all warps done READING fsh before overwrite
#pragma unroll
    for (int k = 0; k < 5; k++) {
        fsh[l0 + 0][lane + 32 * k] = acc[0][k];
        fsh[l0 + 1][lane + 32 * k] = acc[1][k];
        fsh[l0 + 2][lane + 32 * k] = acc[2][k];
        fsh[l0 + 3][lane + 32 * k] = acc[3][k];
    }
    __syncthreads();

    if (MODE == 0) {
        for (int idx = tid; idx < 32 * 160; idx += 256) {
            int l = idx / 160;
            int j = idx - l * 160;
            out[base + idx] = fsh[l][j];
        }
    } else {
        for (int idx = tid; idx < 32 * 160; idx += 256) {
            int j = idx >> 5;
            int l = idx & 31;
            out[base + (long)j * stride + l] = fsh[l][j];
        }
    }
}

// ---------------------------------------------------------------------------
// Separable 3x3x3 neighborhood max on d^2 (in g_A), then skeleton test and
// multiply by img.   g_A -x-> g_B -y-> g_C ; final uses g_A, g_C, img.
// ---------------------------------------------------------------------------
__global__ __launch_bounds__(256) void max_x_kernel()
{
    int idx = blockIdx.x * 256 + threadIdx.x;
    if (idx >= NTOT) return;
    int x = idx % 160;
    float m = g_A[idx];
    if (x > 0)   m = fmaxf(m, g_A[idx - 1]);
    if (x < 159) m = fmaxf(m, g_A[idx + 1]);
    g_B[idx] = m;
}

__global__ __launch_bounds__(256) void max_y_kernel()
{
    int idx = blockIdx.x * 256 + threadIdx.x;
    if (idx >= NTOT) return;
    int y = (idx / 160) % 160;
    float m = g_B[idx];
    if (y > 0)   m = fmaxf(m, g_B[idx - 160]);
    if (y < 159) m = fmaxf(m, g_B[idx + 160]);
    g_C[idx] = m;
}

__global__ __launch_bounds__(256) void final_kernel(const float* __restrict__ img,
                                                    float* __restrict__ out)
{
    int idx = blockIdx.x * 256 + threadIdx.x;
    if (idx >= NTOT) return;
    int z = (idx / HWSZ) % 160;
    float m = g_C[idx];
    if (z > 0)   m = fmaxf(m, g_C[idx - HWSZ]);
    if (z < 159) m = fmaxf(m, g_C[idx + HWSZ]);
    float c = g_A[idx];
    out[idx] = (c >= m && c > 0.0f) ? img[idx] : 0.0f;
}

// ---------------------------------------------------------------------------
extern "C" void kernel_launch(void* const* d_in, const int* in_sizes, int n_in,
                              void* d_out, int out_size)
{
    const float* img = (const float*)d_in[0];
    float* out = (float*)d_out;

    // EDT: x -> y -> z  (g_A holds final d^2)
    edt_pass_kernel<0><<<3200, 256>>>(img);
    edt_pass_kernel<1><<<3200, 256>>>(nullptr);
    edt_pass_kernel<2><<<3200, 256>>>(nullptr);

    // Separable 3x3x3 max of d^2
    max_x_kernel<<<64000, 256>>>();
    max_y_kernel<<<64000, 256>>>();

    // z-max + skeleton test + multiply by img
    final_kernel<<<64000, 256>>>(img, out);
}

// round 3
// speedup vs baseline: 2.5539x; 2.5539x over previous
#include <cuda_runtime.h>

// DMTSkeletonize: exact squared-EDT with adaptive candidate window (bit-exact
// vs brute force: any j with (i-j)^2 >= running-min can't change the min since
// f >= 0), plus a single fused 3x3x3 local-max skeleton kernel on d^2.
//
// Shapes: img [4,1,160,160,160] fp32. B=4, D=H=W=160.

#define WW    160
#define HWSZ  25600      // H*W
#define DHWSZ 4096000    // D*H*W
#define NTOT  16384000   // B*D*H*W
#define FINF  1e12f

// Scratch (device globals — no allocation anywhere, per harness rules)
__device__ float g_A[NTOT];
__device__ float g_B[NTOT];

// ---------------------------------------------------------------------------
// EDT 1D pass: out[line][i] = min_j fl(f[line][j] + (i-j)^2)
// MODE 0: lines along x (contiguous); input = img binarized; writes g_A
// MODE 1: lines along y (stride W);   g_A -> g_B
// MODE 2: lines along z (stride H*W); g_B -> g_A
// Block: 256 threads, 32 lines/block. Compute: thread = (line, segment-of-20),
// adaptive outward scan per output, early exit when k^2 >= acc.
// ---------------------------------------------------------------------------
template <int MODE>
__global__ __launch_bounds__(256) void edt_pass_kernel(const float* __restrict__ img)
{
    __shared__ float fsh[32][161];  // pad: conflict-free transposed access

    const float* __restrict__ in  = (MODE == 0) ? img : (MODE == 1 ? g_A : g_B);
    float* __restrict__       out = (MODE == 1) ? g_B : g_A;

    const int tid = threadIdx.x;
    const int bid = blockIdx.x;

    long base;
    int stride;
    if (MODE == 0) {
        base = (long)bid * (32 * 160);
        stride = 1;
    } else if (MODE == 1) {
        int p  = bid / 5;            // p = b*160 + z
        int x0 = (bid % 5) * 32;
        base = (long)p * HWSZ + x0;
        stride = WW;
    } else {
        int p  = bid / 5;            // p = b*160 + y
        int x0 = (bid % 5) * 32;
        int b = p / 160, y = p - b * 160;
        base = (long)b * DHWSZ + (long)y * WW + x0;
        stride = HWSZ;
    }

    // ---- load tile into shared (coalesced) ----
    if (MODE == 0) {
        for (int idx = tid; idx < 32 * 160; idx += 256) {
            int l = idx / 160;
            int j = idx - l * 160;
            float v = in[base + idx];
            fsh[l][j] = (v > 0.5f) ? 0.0f : FINF;     // binarize + invert
        }
    } else {
        for (int idx = tid; idx < 32 * 160; idx += 256) {
            int j = idx >> 5;
            int l = idx & 31;
            fsh[l][j] = in[base + (long)j * stride + l];
        }
    }
    __syncthreads();

    // ---- adaptive-window min-plus transform ----
    const int l = tid >> 3;          // line 0..31
    const int s = tid & 7;           // segment 0..7 (20 outputs each)
    const float* __restrict__ f = fsh[l];

    float res[20];
#pragma unroll 1
    for (int o = 0; o < 20; o++) {
        const int i = s * 20 + o;
        float acc = f[i];            // j = i term: fl(f+0) = f exactly
#pragma unroll 1
        for (int k = 1; k < 160; k++) {
            const float kk = (float)(k * k);        // exact in fp32
            if (kk >= acc) break;                   // no further j can win
            const int jn = i - k, jp = i + k;
            if (jn >= 0)  acc = fminf(acc, kk + f[jn]);   // 1 rounding = ref
            if (jp < 160) acc = fminf(acc, kk + f[jp]);
        }
        res[o] = acc;
    }

    __syncthreads();   // all reads of fsh done before overwrite
#pragma unroll
    for (int o = 0; o < 20; o++) fsh[l][s * 20 + o] = res[o];
    __syncthreads();

    // ---- coalesced store ----
    if (MODE == 0) {
        for (int idx = tid; idx < 32 * 160; idx += 256) {
            int ll = idx / 160;
            int j  = idx - ll * 160;
            out[base + idx] = fsh[ll][j];
        }
    } else {
        for (int idx = tid; idx < 32 * 160; idx += 256) {
            int j  = idx >> 5;
            int ll = idx & 31;
            out[base + (long)j * stride + ll] = fsh[ll][j];
        }
    }
}

// ---------------------------------------------------------------------------
// Fused 3x3x3 neighborhood max (separable in shared) + skeleton + multiply.
// Tile 32(x) x 8(y) x 4(z) per block, halo 34x10x6. grid = (5, 20, 40*4).
// ---------------------------------------------------------------------------
#define TX 32
#define TY 8
#define TZ 4

__global__ __launch_bounds__(256) void skel_kernel(const float* __restrict__ img,
                                                   float* __restrict__ out)
{
    __shared__ float sA[TZ + 2][TY + 2][TX + 2];  // raw halo      6*10*34
    __shared__ float sB[TZ + 2][TY + 2][TX];      // x-max         6*10*32
    __shared__ float sC[TZ + 2][TY][TX];          // xy-max        6* 8*32

    const int tid = threadIdx.x;
    const int x0 = blockIdx.x * TX;
    const int y0 = blockIdx.y * TY;
    const int zb = blockIdx.z;           // 0..159
    const int b  = zb / 40;
    const int z0 = (zb - b * 40) * TZ;
    const long gbase = (long)b * DHWSZ;
    const float* __restrict__ A = g_A + gbase;

    // load halo (OOB = -inf, matching reduce_window padding)
    for (int idx = tid; idx < (TZ + 2) * (TY + 2) * (TX + 2); idx += 256) {
        int hx = idx % (TX + 2);
        int t  = idx / (TX + 2);
        int hy = t % (TY + 2);
        int hz = t / (TY + 2);
        int gx = x0 + hx - 1, gy = y0 + hy - 1, gz = z0 + hz - 1;
        float v = -3.0e38f;
        if (gx >= 0 && gx < 160 && gy >= 0 && gy < 160 && gz >= 0 && gz < 160)
            v = A[(long)gz * HWSZ + gy * WW + gx];
        sA[hz][hy][hx] = v;
    }
    __syncthreads();

    // x-max
    for (int idx = tid; idx < (TZ + 2) * (TY + 2) * TX; idx += 256) {
        int x  = idx & (TX - 1);
        int t  = idx >> 5;
        int hy = t % (TY + 2);
        int hz = t / (TY + 2);
        sB[hz][hy][x] = fmaxf(fmaxf(sA[hz][hy][x], sA[hz][hy][x + 1]), sA[hz][hy][x + 2]);
    }
    __syncthreads();

    // y-max
    for (int idx = tid; idx < (TZ + 2) * TY * TX; idx += 256) {
        int x  = idx & (TX - 1);
        int t  = idx >> 5;
        int y  = t % TY;
        int hz = t / TY;
        sC[hz][y][x] = fmaxf(fmaxf(sB[hz][y][x], sB[hz][y + 1][x]), sB[hz][y + 2][x]);
    }
    __syncthreads();

    // z-max + skeleton test + multiply by img (coalesced global I/O)
    const int x = tid & 31;
    const int y = tid >> 5;     // 0..7
#pragma unroll
    for (int z = 0; z < TZ; z++) {
        float m = fmaxf(fmaxf(sC[z][y][x], sC[z + 1][y][x]), sC[z + 2][y][x]);
        float c = sA[z + 1][y + 1][x + 1];
        long gi = gbase + (long)(z0 + z) * HWSZ + (y0 + y) * WW + (x0 + x);
        out[gi] = (c >= m && c > 0.0f) ? img[gi] : 0.0f;
    }
}

// ---------------------------------------------------------------------------
extern "C" void kernel_launch(void* const* d_in, const int* in_sizes, int n_in,
                              void* d_out, int out_size)
{
    const float* img = (const float*)d_in[0];
    float* out = (float*)d_out;

    // EDT: x -> y -> z  (g_A holds final d^2)
    edt_pass_kernel<0><<<3200, 256>>>(img);
    edt_pass_kernel<1><<<3200, 256>>>(nullptr);
    edt_pass_kernel<2><<<3200, 256>>>(nullptr);

    // Fused 3x3x3 max + skeleton + multiply
    skel_kernel<<<dim3(5, 20, 160), 256>>>(img, out);
}